// round 14
// baseline (speedup 1.0000x reference)
#include <cuda_runtime.h>
#include <cuda_bf16.h>
#include <math.h>

// FINAL — best measured configuration (R5/R8/R12: 75.8-76.5us, DRAM ~82%,
// 6.48 TB/s effective = hardware memset ceiling for this 512 MiB stream).
//
// Static shapes: B=2048, D=256, K = D/2-1 = 127. Output R[2048,256,256] fp32
// (512 MiB, ~0.6% nonzero). Pure HBM-write-bound.
//
// Nonzeros (even rows r only):
//   col r-2 -> sin(p*theta_{(r-2)/2})    (r >= 2)
//   col r   -> cos(p*theta_{min(r/2,126)})
//   col r+2 -> -sin(p*theta_{r/2})       (r/2 <= 126)
// theta_i = 10000^(-2*(i-1)/256), theta computed in double then fp32 so the
// fp32 phase p*theta matches the reference to ~1 ulp (rel_err 2.9e-8).
//
// Grid: 8192 blocks = 2048 matrices x 4 chunks. Chunk q owns row-groups
// kp in [16q, 16q+16) (group = 4 rows = 256 quads). Thread tid = h*64+j
// writes quad (kp*256 + tid) for each kp: 16 warp-uniform STG.128 of zeros
// (36-lane table build overlaps underneath), then <=2 patch STG.128
// overwriting the near-diagonal quads (same thread, same address -> program
// order, patch wins).
//
// Tested and rejected (keep the zero loop as bare STG.128 of a fixed zero
// quad — nothing else in the body):
//   - eviction-hint variants: neutral (R6) or -17% (R10, L2-way stealing)
//   - skip-patch predication: -40% (R7, fragments warp-uniform stores)
//   - per-iteration value select: -38% (R13, regs 26->40, occ 83->55,
//     alu 19%; select cost >> the 1.6% double-write it saves)
//   - 256-bit v8.b32 zeros: neutral (R11)
//   - per-element fused decode: 10x regress (R3)
//   - memset + scatter kernel: +18.8us serialized tail (R1)

#define K_ITERS 127

__global__ __launch_bounds__(256) void rope_kernel(float4* __restrict__ out) {
    // Table slice: indices i = off + t, t in [0,36), off = 2*k0 - 1.
    __shared__ float s_c[36];
    __shared__ float s_s[36];

    const int tid = threadIdx.x;
    const int p   = blockIdx.x >> 2;
    const int q   = blockIdx.x & 3;
    const int k0  = q << 4;              // first row-group of this chunk
    const int off = 2 * k0 - 1;

    // Phase 1a: table slice (2 warps of heavy math; overlaps with zeros below).
    if (tid < 36) {
        const int i = off + tid;
        if (i >= 0 && i < K_ITERS) {
            const double e = -2.0 * ((double)i - 1.0) / 256.0;
            const float theta = (float)exp(e * 9.210340371976184);  // ln(10000)
            const float m = (float)p * theta;
            s_s[tid] = sinf(m);
            s_c[tid] = cosf(m);
        }
    }

    // Phase 1b: stream zeros for this chunk (no dependence on the table).
    float4* mbase = out + ((size_t)p << 14) + tid;        // matrix base + tid
    float4* zbase = mbase + ((size_t)k0 << 8);            // chunk base
    const float4 z = make_float4(0.f, 0.f, 0.f, 0.f);
#pragma unroll
    for (int k = 0; k < 16; k++) {
        __stcs(&zbase[k << 8], z);       // STG.E.128.CS [R + k*4096], zeros
    }

    __syncthreads();

    // Phase 2: patches. SSx/SCx index the slice.
#define SSx(i) s_s[(i) - off]
#define SCx(i) s_c[(i) - off]
    const int h = tid >> 6;
    const int j = tid & 63;
    const int k1 = k0 + 16;
    if (h == 0) {
        // row 4j, quad j: .x = cos_{2j}, .z = -sin_{2j}
        if (j >= k0 && j < k1)
            mbase[j << 8] = make_float4(SCx(2 * j), 0.f, -SSx(2 * j), 0.f);
        // row 4j+4, quad j: .z = sin_{2j+1}
        if (j <= 62 && (j + 1) >= k0 && (j + 1) < k1)
            mbase[(j + 1) << 8] = make_float4(0.f, 0.f, SSx(2 * j + 1), 0.f);
    } else if (h == 2) {
        // row 4j+2, quad j: .x = sin_{2j}, .z = cos_{min(2j+1,126)}
        if (j >= k0 && j < k1) {
            int i = 2 * j + 1; if (i > K_ITERS - 1) i = K_ITERS - 1;
            mbase[j << 8] = make_float4(SSx(2 * j), 0.f, SCx(i), 0.f);
        }
        // row 4j-2, quad j: .x = -sin_{2j-1}
        if (j >= 1 && (j - 1) >= k0 && (j - 1) < k1)
            mbase[(j - 1) << 8] = make_float4(-SSx(2 * j - 1), 0.f, 0.f, 0.f);
    }
#undef SSx
#undef SCx
}

extern "C" void kernel_launch(void* const* d_in, const int* in_sizes, int n_in,
                              void* d_out, int out_size) {
    (void)d_in; (void)in_sizes; (void)n_in; (void)out_size;
    rope_kernel<<<8192, 256, 0, 0>>>((float4*)d_out);
}

// round 15
// speedup vs baseline: 1.3811x; 1.3811x over previous
#include <cuda_runtime.h>
#include <cuda_bf16.h>
#include <math.h>

// FINAL configuration — unchanged resubmission for re-measurement.
// Five prior runs of this exact structure (R5, R6, R8, R11, R12) measured
// 73.5-75.3us kernel / 75.8-76.5us wall, DRAM 80-82% (6.4-6.5 TB/s, the
// hardware memset ceiling for a 512 MiB write stream). R14 ran byte-identical
// source at 104.7us with DRAM 57.7% — an environment outlier (DVFS/co-tenant),
// not a code property. Re-benching per rigor.md.
//
// Static shapes: B=2048, D=256, K = D/2-1 = 127. Output R[2048,256,256] fp32.
// Nonzeros (even rows r only):
//   col r-2 -> sin(p*theta_{(r-2)/2})    (r >= 2)
//   col r   -> cos(p*theta_{min(r/2,126)})
//   col r+2 -> -sin(p*theta_{r/2})       (r/2 <= 126)
// theta_i = 10000^(-2*(i-1)/256), theta in double then fp32 (rel_err 2.9e-8).
//
// Grid: 8192 blocks = 2048 matrices x 4 chunks. Chunk q owns row-groups
// [16q, 16q+16). Thread tid writes quad (kp*256 + tid) per group: 16
// warp-uniform STG.128 zeros (36-lane table build overlaps), then <=2 patch
// STG.128 (same thread, same address -> program order, patch wins).
//
// Rejected by measurement: eviction hints (neutral/-17%), skip-patch
// predication (-40%), per-iteration select (-38%), v8.b32 (neutral),
// per-element decode (10x), memset+scatter (+18.8us tail).

#define K_ITERS 127

__global__ __launch_bounds__(256) void rope_kernel(float4* __restrict__ out) {
    // Table slice: indices i = off + t, t in [0,36), off = 2*k0 - 1.
    __shared__ float s_c[36];
    __shared__ float s_s[36];

    const int tid = threadIdx.x;
    const int p   = blockIdx.x >> 2;
    const int q   = blockIdx.x & 3;
    const int k0  = q << 4;              // first row-group of this chunk
    const int off = 2 * k0 - 1;

    // Phase 1a: table slice (2 warps of heavy math; overlaps with zeros below).
    if (tid < 36) {
        const int i = off + tid;
        if (i >= 0 && i < K_ITERS) {
            const double e = -2.0 * ((double)i - 1.0) / 256.0;
            const float theta = (float)exp(e * 9.210340371976184);  // ln(10000)
            const float m = (float)p * theta;
            s_s[tid] = sinf(m);
            s_c[tid] = cosf(m);
        }
    }

    // Phase 1b: stream zeros for this chunk (no dependence on the table).
    float4* mbase = out + ((size_t)p << 14) + tid;        // matrix base + tid
    float4* zbase = mbase + ((size_t)k0 << 8);            // chunk base
    const float4 z = make_float4(0.f, 0.f, 0.f, 0.f);
#pragma unroll
    for (int k = 0; k < 16; k++) {
        __stcs(&zbase[k << 8], z);       // STG.E.128.CS [R + k*4096], zeros
    }

    __syncthreads();

    // Phase 2: patches. SSx/SCx index the slice.
#define SSx(i) s_s[(i) - off]
#define SCx(i) s_c[(i) - off]
    const int h = tid >> 6;
    const int j = tid & 63;
    const int k1 = k0 + 16;
    if (h == 0) {
        // row 4j, quad j: .x = cos_{2j}, .z = -sin_{2j}
        if (j >= k0 && j < k1)
            mbase[j << 8] = make_float4(SCx(2 * j), 0.f, -SSx(2 * j), 0.f);
        // row 4j+4, quad j: .z = sin_{2j+1}
        if (j <= 62 && (j + 1) >= k0 && (j + 1) < k1)
            mbase[(j + 1) << 8] = make_float4(0.f, 0.f, SSx(2 * j + 1), 0.f);
    } else if (h == 2) {
        // row 4j+2, quad j: .x = sin_{2j}, .z = cos_{min(2j+1,126)}
        if (j >= k0 && j < k1) {
            int i = 2 * j + 1; if (i > K_ITERS - 1) i = K_ITERS - 1;
            mbase[j << 8] = make_float4(SSx(2 * j), 0.f, SCx(i), 0.f);
        }
        // row 4j-2, quad j: .x = -sin_{2j-1}
        if (j >= 1 && (j - 1) >= k0 && (j - 1) < k1)
            mbase[(j - 1) << 8] = make_float4(-SSx(2 * j - 1), 0.f, 0.f, 0.f);
    }
#undef SSx
#undef SCx
}

extern "C" void kernel_launch(void* const* d_in, const int* in_sizes, int n_in,
                              void* d_out, int out_size) {
    (void)d_in; (void)in_sizes; (void)n_in; (void)out_size;
    rope_kernel<<<8192, 256, 0, 0>>>((float4*)d_out);
}